// round 5
// baseline (speedup 1.0000x reference)
#include <cuda_runtime.h>
#include <cuda_bf16.h>

// ---------------------------------------------------------------------------
// Problem constants
// ---------------------------------------------------------------------------
namespace {
constexpr int NB  = 4096;    // batch
constexpr int NN  = 30;      // nodes
constexpr int INC = 512;     // input channels
constexpr int NF  = 128;     // hidden features
constexpr int NC  = 9;       // output channels
constexpr int BPB = 4;       // batches per block (120 rows -> 128 tile)
constexpr int GRID = NB / BPB;

// dynamic smem layout (bytes)
constexpr int OFF_AHI = 0;            // GEMM1 A staging hi  bf16[128][24]
constexpr int OFF_ALO = 6144;         // GEMM1 A staging lo
constexpr int OFF_BHI = 12288;        // GEMM1 B staging hi  bf16[16][136]
constexpr int OFF_BLO = 16640;        // GEMM1 B staging lo          -> 20992
// overlays in region A (after GEMM1):
constexpr int OFF_ANH = 0;            // An hi  bf16[4][32][36] = 9216 B
constexpr int OFF_ANL = 9216;         // An lo
constexpr int OFF_SDI = 18432;        // dinv  float[120]
constexpr int OFF_SX  = 18944;        // x     float[120]
// region B:
constexpr int OFF_XW  = 20992;        // float[128][128]  (XW, later G)
// region C:
constexpr int OFF_CHI = 86528;        // bf16[128][136]  (XW/H1/G hi)
constexpr int OFF_CLO = 121344;       // bf16[128][136]  (lo)
constexpr int OFF_TMPS= 86528;        // overlay: float[4][900] (adjacency pattern)
constexpr int OFF_H2  = 86528;        // overlay: float[120][128] (H2)
// region D:
constexpr int OFF_WHI = 156160;       // W2 hi bf16[128][136]
constexpr int OFF_WLO = 190976;       // W2 lo
constexpr int SMEM_SZ = 225792;
}

// ---------------------------------------------------------------------------
// Helpers
// ---------------------------------------------------------------------------
__device__ __forceinline__ void mma16816(float* c, const unsigned* a, const unsigned* b) {
    asm volatile(
        "mma.sync.aligned.m16n8k16.row.col.f32.bf16.bf16.f32 "
        "{%0,%1,%2,%3}, {%4,%5,%6,%7}, {%8,%9}, {%0,%1,%2,%3};\n"
        : "+f"(c[0]), "+f"(c[1]), "+f"(c[2]), "+f"(c[3])
        : "r"(a[0]), "r"(a[1]), "r"(a[2]), "r"(a[3]),
          "r"(b[0]), "r"(b[1]));
}

__device__ __forceinline__ void store_split4(__nv_bfloat16* hi, __nv_bfloat16* lo, float4 v) {
    __nv_bfloat16 hx = __float2bfloat16_rn(v.x);
    __nv_bfloat16 hy = __float2bfloat16_rn(v.y);
    __nv_bfloat16 hz = __float2bfloat16_rn(v.z);
    __nv_bfloat16 hw = __float2bfloat16_rn(v.w);
    *(__nv_bfloat162*)(hi)     = __halves2bfloat162(hx, hy);
    *(__nv_bfloat162*)(hi + 2) = __halves2bfloat162(hz, hw);
    *(__nv_bfloat162*)(lo)     = __floats2bfloat162_rn(v.x - __bfloat162float(hx),
                                                       v.y - __bfloat162float(hy));
    *(__nv_bfloat162*)(lo + 2) = __floats2bfloat162_rn(v.z - __bfloat162float(hz),
                                                       v.w - __bfloat162float(hw));
}

__device__ __forceinline__ void split_store2(__nv_bfloat16* hp, __nv_bfloat16* lp,
                                             float x, float y) {
    __nv_bfloat16 hx = __float2bfloat16_rn(x);
    __nv_bfloat16 hy = __float2bfloat16_rn(y);
    *(__nv_bfloat162*)hp = __halves2bfloat162(hx, hy);
    *(__nv_bfloat162*)lp = __floats2bfloat162_rn(x - __bfloat162float(hx),
                                                 y - __bfloat162float(hy));
}

__device__ __forceinline__ unsigned pack2(const __nv_bfloat16* p0, const __nv_bfloat16* p1) {
    unsigned u0 = *(const unsigned short*)p0;
    unsigned u1 = *(const unsigned short*)p1;
    return u0 | (u1 << 16);
}

// Block-diagonal prop GEMM for one batch: C[32x128] = An[32x32] @ X[32x128],
// split-bf16 3-pass. Warp covers 64 N-cols (nhalf). Operand strides: An 36, X 136.
__device__ __forceinline__ void prop_mma(
    const __nv_bfloat16* __restrict__ anh, const __nv_bfloat16* __restrict__ anl,
    const __nv_bfloat16* __restrict__ xh,  const __nv_bfloat16* __restrict__ xl,
    int nhalf, int g, int tq, float pacc[2][8][4])
{
#pragma unroll
    for (int mt = 0; mt < 2; mt++)
#pragma unroll
        for (int nt = 0; nt < 8; nt++)
#pragma unroll
            for (int q = 0; q < 4; q++) pacc[mt][nt][q] = 0.f;

#pragma unroll
    for (int kk = 0; kk < 2; kk++) {
        const int kc = kk * 16 + 2 * tq;
        unsigned ah[2][4], al[2][4];
#pragma unroll
        for (int mt = 0; mt < 2; mt++) {
            const int r = mt * 16 + g;
            ah[mt][0] = *(const unsigned*)&anh[r * 36 + kc];
            ah[mt][1] = *(const unsigned*)&anh[(r + 8) * 36 + kc];
            ah[mt][2] = *(const unsigned*)&anh[r * 36 + kc + 8];
            ah[mt][3] = *(const unsigned*)&anh[(r + 8) * 36 + kc + 8];
            al[mt][0] = *(const unsigned*)&anl[r * 36 + kc];
            al[mt][1] = *(const unsigned*)&anl[(r + 8) * 36 + kc];
            al[mt][2] = *(const unsigned*)&anl[r * 36 + kc + 8];
            al[mt][3] = *(const unsigned*)&anl[(r + 8) * 36 + kc + 8];
        }
#pragma unroll
        for (int nt = 0; nt < 8; nt++) {
            const int n = nhalf * 64 + nt * 8 + g;
            unsigned bh[2], bl[2];
            bh[0] = pack2(&xh[kc * 136 + n],       &xh[(kc + 1) * 136 + n]);
            bh[1] = pack2(&xh[(kc + 8) * 136 + n], &xh[(kc + 9) * 136 + n]);
            bl[0] = pack2(&xl[kc * 136 + n],       &xl[(kc + 1) * 136 + n]);
            bl[1] = pack2(&xl[(kc + 8) * 136 + n], &xl[(kc + 9) * 136 + n]);
#pragma unroll
            for (int mt = 0; mt < 2; mt++) {
                mma16816(pacc[mt][nt], ah[mt], bh);
                mma16816(pacc[mt][nt], ah[mt], bl);
                mma16816(pacc[mt][nt], al[mt], bh);
            }
        }
    }
}

// ---------------------------------------------------------------------------
// Fully fused kernel: one block = 4 batches, end to end.
// ---------------------------------------------------------------------------
__global__ void __launch_bounds__(256) fused_gcn_kernel(
    const float* __restrict__ real,  const float* __restrict__ graph,
    const float* __restrict__ W1,    const float* __restrict__ b1,
    const float* __restrict__ W2,    const float* __restrict__ b2,
    const float* __restrict__ Wlin,  const float* __restrict__ blin,
    const float* __restrict__ Wconv, const float* __restrict__ bconv,
    float* __restrict__ out)
{
    extern __shared__ __align__(16) char smem[];

    const int tid  = threadIdx.x;
    const int warp = tid >> 5, lane = tid & 31;
    const int wm = warp >> 2, wn = warp & 3;   // 2x4 warp grid (GEMM phases)
    const int g  = lane >> 2, tq = lane & 3;
    const int b0 = blockIdx.x * BPB;
    const long rowbase = (long)b0 * NN;

    __nv_bfloat16* sAhi = (__nv_bfloat16*)(smem + OFF_AHI);
    __nv_bfloat16* sAlo = (__nv_bfloat16*)(smem + OFF_ALO);
    __nv_bfloat16* sBhi = (__nv_bfloat16*)(smem + OFF_BHI);
    __nv_bfloat16* sBlo = (__nv_bfloat16*)(smem + OFF_BLO);
    float*         sXW  = (float*)(smem + OFF_XW);     // also G
    __nv_bfloat16* ch   = (__nv_bfloat16*)(smem + OFF_CHI);
    __nv_bfloat16* cl   = (__nv_bfloat16*)(smem + OFF_CLO);
    __nv_bfloat16* wh   = (__nv_bfloat16*)(smem + OFF_WHI);
    __nv_bfloat16* wl   = (__nv_bfloat16*)(smem + OFF_WLO);
    __nv_bfloat16* anh  = (__nv_bfloat16*)(smem + OFF_ANH);
    __nv_bfloat16* anl  = (__nv_bfloat16*)(smem + OFF_ANL);
    float*         sdi  = (float*)(smem + OFF_SDI);
    float*         sx   = (float*)(smem + OFF_SX);
    float*         tmpS = (float*)(smem + OFF_TMPS);
    float*         sH2  = (float*)(smem + OFF_H2);

    // ======================= Phase 1: GEMM1  XW = real @ W1 ==================
    float acc[4][4][4];
#pragma unroll
    for (int a = 0; a < 4; a++)
#pragma unroll
        for (int b = 0; b < 4; b++)
#pragma unroll
            for (int c = 0; c < 4; c++) acc[a][b][c] = 0.f;

    const int rA0 = tid >> 2;           // 0..63 (and +64)
    const int kA0 = (tid & 3) * 4;
    const int rB0 = tid >> 5;
    const int nB0 = (tid & 31) * 4;
    const int ra0 = (rA0      < 120) ? rA0      : 119;   // clamp pad rows
    const int ra1 = (rA0 + 64 < 120) ? rA0 + 64 : 119;

    const float* Ap0 = real + (rowbase + ra0) * INC + kA0;
    const float* Ap1 = real + (rowbase + ra1) * INC + kA0;
    const float* Bp0 = W1 + rB0 * NF + nB0;
    const float* Bp1 = Bp0 + 8 * NF;

    float4 ra = *(const float4*)Ap0;
    float4 rb = *(const float4*)Ap1;
    float4 wa = *(const float4*)Bp0;
    float4 wb = *(const float4*)Bp1;

    for (int it = 0; it < INC / 16; ++it) {
        store_split4(sAhi + rA0 * 24 + kA0,        sAlo + rA0 * 24 + kA0,        ra);
        store_split4(sAhi + (rA0 + 64) * 24 + kA0, sAlo + (rA0 + 64) * 24 + kA0, rb);
        store_split4(sBhi + rB0 * 136 + nB0,       sBlo + rB0 * 136 + nB0,       wa);
        store_split4(sBhi + (rB0 + 8) * 136 + nB0, sBlo + (rB0 + 8) * 136 + nB0, wb);
        __syncthreads();

        if (it + 1 < INC / 16) {
            ra = *(const float4*)(Ap0 + (it + 1) * 16);
            rb = *(const float4*)(Ap1 + (it + 1) * 16);
            wa = *(const float4*)(Bp0 + (long)(it + 1) * 16 * NF);
            wb = *(const float4*)(Bp1 + (long)(it + 1) * 16 * NF);
        }

        unsigned bh[4][2], blx[4][2];
#pragma unroll
        for (int nt = 0; nt < 4; nt++) {
            const int n = wn * 32 + nt * 8 + g;
            bh[nt][0]  = pack2(&sBhi[(2 * tq) * 136 + n],     &sBhi[(2 * tq + 1) * 136 + n]);
            bh[nt][1]  = pack2(&sBhi[(2 * tq + 8) * 136 + n], &sBhi[(2 * tq + 9) * 136 + n]);
            blx[nt][0] = pack2(&sBlo[(2 * tq) * 136 + n],     &sBlo[(2 * tq + 1) * 136 + n]);
            blx[nt][1] = pack2(&sBlo[(2 * tq + 8) * 136 + n], &sBlo[(2 * tq + 9) * 136 + n]);
        }
#pragma unroll
        for (int mt = 0; mt < 4; mt++) {
            const int r = wm * 64 + mt * 16 + g;
            unsigned ah[4], al[4];
            ah[0] = *(const unsigned*)&sAhi[r * 24 + 2 * tq];
            ah[1] = *(const unsigned*)&sAhi[(r + 8) * 24 + 2 * tq];
            ah[2] = *(const unsigned*)&sAhi[r * 24 + 2 * tq + 8];
            ah[3] = *(const unsigned*)&sAhi[(r + 8) * 24 + 2 * tq + 8];
            al[0] = *(const unsigned*)&sAlo[r * 24 + 2 * tq];
            al[1] = *(const unsigned*)&sAlo[(r + 8) * 24 + 2 * tq];
            al[2] = *(const unsigned*)&sAlo[r * 24 + 2 * tq + 8];
            al[3] = *(const unsigned*)&sAlo[(r + 8) * 24 + 2 * tq + 8];
#pragma unroll
            for (int nt = 0; nt < 4; nt++) {
                mma16816(acc[mt][nt], ah, bh[nt]);
                mma16816(acc[mt][nt], ah, blx[nt]);
                mma16816(acc[mt][nt], al, bh[nt]);
            }
        }
        __syncthreads();
    }

    // ======== Phase 2a: dump XW, adjacency pattern, W2 split, An-pad zero ====
#pragma unroll
    for (int mt = 0; mt < 4; mt++) {
        const int row = wm * 64 + mt * 16 + g;
#pragma unroll
        for (int nt = 0; nt < 4; nt++) {
            const int col = wn * 32 + nt * 8 + 2 * tq;
            *(float2*)&sXW[row * 128 + col]       = make_float2(acc[mt][nt][0], acc[mt][nt][1]);
            *(float2*)&sXW[(row + 8) * 128 + col] = make_float2(acc[mt][nt][2], acc[mt][nt][3]);
        }
    }
    {   // zero An buffers (covers K-pad cols 30..35 and rows 30,31)
        const __nv_bfloat16 z = __float2bfloat16_rn(0.f);
        for (int idx = tid; idx < BPB * 32 * 36; idx += 256) { anh[idx] = z; anl[idx] = z; }
    }
    for (int idx = tid; idx < BPB * 900; idx += 256) {   // adjacency pattern
        const int b = idx / 900, rem = idx - b * 900;
        const float* gb = graph + ((size_t)(b0 + b) * 5) * 900 + rem;
        const float s = gb[0] + gb[900] + gb[1800] + gb[2700] + gb[3600];
        const int i = rem / 30, j = rem - i * 30;
        tmpS[idx] = (s != 0.0f || i == j) ? 1.0f : 0.0f;
    }
    for (int idx = tid; idx < 128 * 128 / 4; idx += 256) {   // W2 -> hi/lo
        const int k = idx >> 5, n4 = (idx & 31) * 4;
        float4 v = *(const float4*)(W2 + k * 128 + n4);
        store_split4(wh + k * 136 + n4, wl + k * 136 + n4, v);
    }
    __syncthreads();

    if (tid < BPB * NN) {                 // degrees -> dinv
        const int b = tid / NN, i = tid - b * NN;
        const float* rowp = tmpS + b * 900 + i * 30;
        float d = 0.f;
#pragma unroll
        for (int j = 0; j < NN; j++) d += rowp[j];
        sdi[tid] = rsqrtf(d);
    }
    __syncthreads();

    for (int idx = tid; idx < BPB * 900; idx += 256) {   // An -> hi/lo bf16
        const int b = idx / 900, rem = idx - b * 900;
        const int i = rem / 30, j = rem - i * 30;
        const float v = sdi[b * 30 + i] * tmpS[idx] * sdi[b * 30 + j];
        const __nv_bfloat16 h = __float2bfloat16_rn(v);
        anh[(b * 32 + i) * 36 + j] = h;
        anl[(b * 32 + i) * 36 + j] = __float2bfloat16_rn(v - __bfloat162float(h));
    }
    __syncthreads();

    // ============ Phase 2b: convert XW (fp32) -> hi/lo in region C ===========
    for (int idx = tid; idx < 128 * 128 / 4; idx += 256) {
        const int r = idx >> 5, c4 = (idx & 31) * 4;
        float4 v = *(const float4*)&sXW[r * 128 + c4];
        store_split4(ch + r * 136 + c4, cl + r * 136 + c4, v);
    }
    __syncthreads();

    // ============ Phase 3: prop1  H1 = relu(An @ XW + b1)  (MMA) =============
    const int bq = warp >> 1, nhalf = warp & 1;    // warp -> (batch, N-half)
    {
        float pacc[2][8][4];
        prop_mma(anh + bq * 32 * 36, anl + bq * 32 * 36,
                 ch + bq * 30 * 136, cl + bq * 30 * 136, nhalf, g, tq, pacc);
        __syncthreads();    // WAR: region C reads done before H1 overwrite
#pragma unroll
        for (int mt = 0; mt < 2; mt++) {
#pragma unroll
            for (int nt = 0; nt < 8; nt++) {
                const int n = nhalf * 64 + nt * 8 + 2 * tq;
                const float bx = __ldg(b1 + n), by = __ldg(b1 + n + 1);
                const int i0 = mt * 16 + g;
                if (i0 < NN) {
                    split_store2(&ch[(bq * 30 + i0) * 136 + n], &cl[(bq * 30 + i0) * 136 + n],
                                 fmaxf(pacc[mt][nt][0] + bx, 0.f),
                                 fmaxf(pacc[mt][nt][1] + by, 0.f));
                }
                const int i1 = i0 + 8;
                if (i1 < NN) {
                    split_store2(&ch[(bq * 30 + i1) * 136 + n], &cl[(bq * 30 + i1) * 136 + n],
                                 fmaxf(pacc[mt][nt][2] + bx, 0.f),
                                 fmaxf(pacc[mt][nt][3] + by, 0.f));
                }
            }
        }
        __syncthreads();
    }

    // ============ Phase 4: GEMM2  G = H1 @ W2 (K=128, resident) ==============
#pragma unroll
    for (int a = 0; a < 4; a++)
#pragma unroll
        for (int b = 0; b < 4; b++)
#pragma unroll
            for (int c = 0; c < 4; c++) acc[a][b][c] = 0.f;

#pragma unroll
    for (int it = 0; it < 8; ++it) {
        const int ko = it * 16 + 2 * tq;
        unsigned bh[4][2], blx[4][2];
#pragma unroll
        for (int nt = 0; nt < 4; nt++) {
            const int n = wn * 32 + nt * 8 + g;
            bh[nt][0]  = pack2(&wh[ko * 136 + n],       &wh[(ko + 1) * 136 + n]);
            bh[nt][1]  = pack2(&wh[(ko + 8) * 136 + n], &wh[(ko + 9) * 136 + n]);
            blx[nt][0] = pack2(&wl[ko * 136 + n],       &wl[(ko + 1) * 136 + n]);
            blx[nt][1] = pack2(&wl[(ko + 8) * 136 + n], &wl[(ko + 9) * 136 + n]);
        }
#pragma unroll
        for (int mt = 0; mt < 4; mt++) {
            const int r = wm * 64 + mt * 16 + g;
            unsigned ah[4], al[4];
            ah[0] = *(const unsigned*)&ch[r * 136 + ko];
            ah[1] = *(const unsigned*)&ch[(r + 8) * 136 + ko];
            ah[2] = *(const unsigned*)&ch[r * 136 + ko + 8];
            ah[3] = *(const unsigned*)&ch[(r + 8) * 136 + ko + 8];
            al[0] = *(const unsigned*)&cl[r * 136 + ko];
            al[1] = *(const unsigned*)&cl[(r + 8) * 136 + ko];
            al[2] = *(const unsigned*)&cl[r * 136 + ko + 8];
            al[3] = *(const unsigned*)&cl[(r + 8) * 136 + ko + 8];
#pragma unroll
            for (int nt = 0; nt < 4; nt++) {
                mma16816(acc[mt][nt], ah, bh[nt]);
                mma16816(acc[mt][nt], ah, blx[nt]);
                mma16816(acc[mt][nt], al, bh[nt]);
            }
        }
    }

    // dump G -> region B (region B free; sync below also covers C WAR)
#pragma unroll
    for (int mt = 0; mt < 4; mt++) {
        const int row = wm * 64 + mt * 16 + g;
#pragma unroll
        for (int nt = 0; nt < 4; nt++) {
            const int col = wn * 32 + nt * 8 + 2 * tq;
            *(float2*)&sXW[row * 128 + col]       = make_float2(acc[mt][nt][0], acc[mt][nt][1]);
            *(float2*)&sXW[(row + 8) * 128 + col] = make_float2(acc[mt][nt][2], acc[mt][nt][3]);
        }
    }
    __syncthreads();

    // convert G -> hi/lo in region C
    for (int idx = tid; idx < 128 * 128 / 4; idx += 256) {
        const int r = idx >> 5, c4 = (idx & 31) * 4;
        float4 v = *(const float4*)&sXW[r * 128 + c4];
        store_split4(ch + r * 136 + c4, cl + r * 136 + c4, v);
    }
    __syncthreads();

    // ============ Phase 5: prop2  H2 = relu(An @ G + b2)  (MMA) ==============
    {
        float pacc[2][8][4];
        prop_mma(anh + bq * 32 * 36, anl + bq * 32 * 36,
                 ch + bq * 30 * 136, cl + bq * 30 * 136, nhalf, g, tq, pacc);
        __syncthreads();    // region C reads done before H2 (fp32) overwrite
#pragma unroll
        for (int mt = 0; mt < 2; mt++) {
#pragma unroll
            for (int nt = 0; nt < 8; nt++) {
                const int n = nhalf * 64 + nt * 8 + 2 * tq;
                const float bx = __ldg(b2 + n), by = __ldg(b2 + n + 1);
                const int i0 = mt * 16 + g;
                if (i0 < NN) {
                    *(float2*)&sH2[(bq * 30 + i0) * 128 + n] =
                        make_float2(fmaxf(pacc[mt][nt][0] + bx, 0.f),
                                    fmaxf(pacc[mt][nt][1] + by, 0.f));
                }
                const int i1 = i0 + 8;
                if (i1 < NN) {
                    *(float2*)&sH2[(bq * 30 + i1) * 128 + n] =
                        make_float2(fmaxf(pacc[mt][nt][2] + bx, 0.f),
                                    fmaxf(pacc[mt][nt][3] + by, 0.f));
                }
            }
        }
        __syncthreads();
    }

    // ============ Phase 6: x = relu(H2 @ Wlin + blin); head ==================
    {
        const float wl0 = __ldg(Wlin + lane),      wl1 = __ldg(Wlin + lane + 32);
        const float wl2 = __ldg(Wlin + lane + 64), wl3 = __ldg(Wlin + lane + 96);
        for (int r = warp; r < BPB * NN; r += 8) {
            float p = sH2[r * 128 + lane] * wl0 + sH2[r * 128 + lane + 32] * wl1 +
                      sH2[r * 128 + lane + 64] * wl2 + sH2[r * 128 + lane + 96] * wl3;
#pragma unroll
            for (int o = 16; o > 0; o >>= 1) p += __shfl_xor_sync(0xffffffffu, p, o);
            if (lane == 0) sx[r] = fmaxf(p + __ldg(blin), 0.f);
        }
    }
    __syncthreads();

    if (tid < BPB * NC) {
        const int b = tid / NC, c = tid - b * NC;
        float a = __ldg(bconv + c);
#pragma unroll
        for (int i = 0; i < NN; i++) a += sx[b * 30 + i] * __ldg(Wconv + c * 30 + i);
        out[(size_t)(b0 + b) * NC + c] = a;
    }
}

// ---------------------------------------------------------------------------
// Launch
// ---------------------------------------------------------------------------
extern "C" void kernel_launch(void* const* d_in, const int* in_sizes, int n_in,
                              void* d_out, int out_size) {
    const float* real  = (const float*)d_in[0];
    // d_in[1] = imag (unused by the reference)
    const float* graph = (const float*)d_in[2];
    const float* W1    = (const float*)d_in[3];
    const float* b1    = (const float*)d_in[4];
    const float* W2    = (const float*)d_in[5];
    const float* b2    = (const float*)d_in[6];
    const float* Wlin  = (const float*)d_in[7];
    const float* blin  = (const float*)d_in[8];
    const float* Wconv = (const float*)d_in[9];
    const float* bconv = (const float*)d_in[10];
    float* out = (float*)d_out;

    cudaFuncSetAttribute(fused_gcn_kernel,
                         cudaFuncAttributeMaxDynamicSharedMemorySize, SMEM_SZ);
    fused_gcn_kernel<<<GRID, 256, SMEM_SZ>>>(real, graph, W1, b1, W2, b2,
                                             Wlin, blin, Wconv, bconv, out);
}

// round 8
// speedup vs baseline: 1.9721x; 1.9721x over previous
#include <cuda_runtime.h>
#include <cuda_bf16.h>

// ---------------------------------------------------------------------------
// Problem constants
// ---------------------------------------------------------------------------
namespace {
constexpr int NB  = 4096;    // batch
constexpr int NN  = 30;      // nodes
constexpr int INC = 512;     // input channels
constexpr int NF  = 128;     // hidden features
constexpr int NC  = 9;       // output channels
constexpr int BPB = 4;       // batches per block in kernel B (120 rows)
constexpr int MROWS = NB * NN;          // 122880

// kernel B dynamic smem layout (bytes)
constexpr int BOFF_CH  = 0;             // bf16[128][136]  XW/H1/G hi
constexpr int BOFF_CL  = 34816;         // lo
constexpr int BOFF_ANH = 69632;         // bf16[4][32][36]
constexpr int BOFF_ANL = 78848;
constexpr int BOFF_TMP = 88064;         // float[4][900] adjacency pattern
constexpr int BOFF_SDI = 102464;        // float[120]
constexpr int BOFF_SXP = 102944;        // float[2][120]
constexpr int BOFF_SX  = 103904;        // float[120]
constexpr int SMEM_B   = 104384;
}

// ---------------------------------------------------------------------------
// Global scratch (allocation forbidden)
// ---------------------------------------------------------------------------
__device__ float    g_XW[(size_t)MROWS * NF];   // GEMM1 output
__device__ unsigned g_W2fh[64 * 128];           // W2 pre-packed mma B-fragments hi
__device__ unsigned g_W2fl[64 * 128];           // lo

// ---------------------------------------------------------------------------
// Helpers
// ---------------------------------------------------------------------------
__device__ __forceinline__ void mma16816(float* c, const unsigned* a, const unsigned* b) {
    asm volatile(
        "mma.sync.aligned.m16n8k16.row.col.f32.bf16.bf16.f32 "
        "{%0,%1,%2,%3}, {%4,%5,%6,%7}, {%8,%9}, {%0,%1,%2,%3};\n"
        : "+f"(c[0]), "+f"(c[1]), "+f"(c[2]), "+f"(c[3])
        : "r"(a[0]), "r"(a[1]), "r"(a[2]), "r"(a[3]),
          "r"(b[0]), "r"(b[1]));
}

__device__ __forceinline__ void store_split4(__nv_bfloat16* hi, __nv_bfloat16* lo, float4 v) {
    __nv_bfloat16 hx = __float2bfloat16_rn(v.x);
    __nv_bfloat16 hy = __float2bfloat16_rn(v.y);
    __nv_bfloat16 hz = __float2bfloat16_rn(v.z);
    __nv_bfloat16 hw = __float2bfloat16_rn(v.w);
    *(__nv_bfloat162*)(hi)     = __halves2bfloat162(hx, hy);
    *(__nv_bfloat162*)(hi + 2) = __halves2bfloat162(hz, hw);
    *(__nv_bfloat162*)(lo)     = __floats2bfloat162_rn(v.x - __bfloat162float(hx),
                                                       v.y - __bfloat162float(hy));
    *(__nv_bfloat162*)(lo + 2) = __floats2bfloat162_rn(v.z - __bfloat162float(hz),
                                                       v.w - __bfloat162float(hw));
}

__device__ __forceinline__ void split_store2(__nv_bfloat16* hp, __nv_bfloat16* lp,
                                             float x, float y) {
    __nv_bfloat16 hx = __float2bfloat16_rn(x);
    __nv_bfloat16 hy = __float2bfloat16_rn(y);
    *(__nv_bfloat162*)hp = __halves2bfloat162(hx, hy);
    *(__nv_bfloat162*)lp = __floats2bfloat162_rn(x - __bfloat162float(hx),
                                                 y - __bfloat162float(hy));
}

__device__ __forceinline__ unsigned pack2(const __nv_bfloat16* p0, const __nv_bfloat16* p1) {
    unsigned u0 = *(const unsigned short*)p0;
    unsigned u1 = *(const unsigned short*)p1;
    return u0 | (u1 << 16);
}

// Block-diagonal prop GEMM for one batch: C[32x128] = An[32x32] @ X[32x128],
// split-bf16 3-pass. Warp covers 64 N-cols (nhalf). Strides: An 36, X 136.
__device__ __forceinline__ void prop_mma(
    const __nv_bfloat16* __restrict__ anh, const __nv_bfloat16* __restrict__ anl,
    const __nv_bfloat16* __restrict__ xh,  const __nv_bfloat16* __restrict__ xl,
    int nhalf, int g, int tq, float pacc[2][8][4])
{
#pragma unroll
    for (int mt = 0; mt < 2; mt++)
#pragma unroll
        for (int nt = 0; nt < 8; nt++)
#pragma unroll
            for (int q = 0; q < 4; q++) pacc[mt][nt][q] = 0.f;

#pragma unroll
    for (int kk = 0; kk < 2; kk++) {
        const int kc = kk * 16 + 2 * tq;
        unsigned ah[2][4], al[2][4];
#pragma unroll
        for (int mt = 0; mt < 2; mt++) {
            const int r = mt * 16 + g;
            ah[mt][0] = *(const unsigned*)&anh[r * 36 + kc];
            ah[mt][1] = *(const unsigned*)&anh[(r + 8) * 36 + kc];
            ah[mt][2] = *(const unsigned*)&anh[r * 36 + kc + 8];
            ah[mt][3] = *(const unsigned*)&anh[(r + 8) * 36 + kc + 8];
            al[mt][0] = *(const unsigned*)&anl[r * 36 + kc];
            al[mt][1] = *(const unsigned*)&anl[(r + 8) * 36 + kc];
            al[mt][2] = *(const unsigned*)&anl[r * 36 + kc + 8];
            al[mt][3] = *(const unsigned*)&anl[(r + 8) * 36 + kc + 8];
        }
#pragma unroll
        for (int nt = 0; nt < 8; nt++) {
            const int n = nhalf * 64 + nt * 8 + g;
            unsigned bh[2], bl[2];
            bh[0] = pack2(&xh[kc * 136 + n],       &xh[(kc + 1) * 136 + n]);
            bh[1] = pack2(&xh[(kc + 8) * 136 + n], &xh[(kc + 9) * 136 + n]);
            bl[0] = pack2(&xl[kc * 136 + n],       &xl[(kc + 1) * 136 + n]);
            bl[1] = pack2(&xl[(kc + 8) * 136 + n], &xl[(kc + 9) * 136 + n]);
#pragma unroll
            for (int mt = 0; mt < 2; mt++) {
                mma16816(pacc[mt][nt], ah[mt], bh);
                mma16816(pacc[mt][nt], ah[mt], bl);
                mma16816(pacc[mt][nt], al[mt], bh);
            }
        }
    }
}

// ---------------------------------------------------------------------------
// Init: pack W2 into mma B-fragment layout (hi/lo).
// P[k2][n] = {W2[2*k2][n], W2[2*k2+1][n]} as bf16x2, k2 in [0,64), n in [0,128).
// ---------------------------------------------------------------------------
__global__ void init_w2frag(const float* __restrict__ W2) {
    const int idx = blockIdx.x * blockDim.x + threadIdx.x;
    if (idx >= 64 * 128) return;
    const int k2 = idx >> 7, n = idx & 127;
    const float w0 = W2[(2 * k2) * 128 + n];
    const float w1 = W2[(2 * k2 + 1) * 128 + n];
    __nv_bfloat16 h0 = __float2bfloat16_rn(w0);
    __nv_bfloat16 h1 = __float2bfloat16_rn(w1);
    __nv_bfloat162 ph = __halves2bfloat162(h0, h1);
    __nv_bfloat162 pl = __floats2bfloat162_rn(w0 - __bfloat162float(h0),
                                              w1 - __bfloat162float(h1));
    g_W2fh[idx] = *(unsigned*)&ph;
    g_W2fl[idx] = *(unsigned*)&pl;
}

// ---------------------------------------------------------------------------
// Kernel A: GEMM1  XW = real @ W1   (split-bf16 3-pass, ping-pong buffers)
// 128x128 block tile, BK=16, 8 warps (2x4), warp tile 64x32. 2 CTAs/SM.
// ---------------------------------------------------------------------------
__global__ void __launch_bounds__(256, 2) gemm1_kernel(const float* __restrict__ A,
                                                       const float* __restrict__ Bw) {
    __shared__ __align__(16) __nv_bfloat16 sAhi[2][128][24];
    __shared__ __align__(16) __nv_bfloat16 sAlo[2][128][24];
    __shared__ __align__(16) __nv_bfloat16 sBhi[2][16][136];
    __shared__ __align__(16) __nv_bfloat16 sBlo[2][16][136];

    const int tid  = threadIdx.x;
    const int warp = tid >> 5, lane = tid & 31;
    const int wm = warp >> 2, wn = warp & 3;
    const int g  = lane >> 2, tq = lane & 3;
    const long mbase = (long)blockIdx.x * 128;

    float acc[4][4][4];
#pragma unroll
    for (int a = 0; a < 4; a++)
#pragma unroll
        for (int b = 0; b < 4; b++)
#pragma unroll
            for (int c = 0; c < 4; c++) acc[a][b][c] = 0.f;

    const int rA0 = tid >> 2;            // 0..63 (and +64)
    const int kA0 = (tid & 3) * 4;
    const int rB0 = tid >> 5;
    const int nB0 = (tid & 31) * 4;

    const float* Ap0 = A + (mbase + rA0) * INC + kA0;
    const float* Ap1 = Ap0 + (long)64 * INC;
    const float* Bp0 = Bw + rB0 * NF + nB0;
    const float* Bp1 = Bp0 + 8 * NF;

    float4 ra = *(const float4*)Ap0;
    float4 rb = *(const float4*)Ap1;
    float4 wa = *(const float4*)Bp0;
    float4 wb = *(const float4*)Bp1;

    store_split4(&sAhi[0][rA0][kA0],      &sAlo[0][rA0][kA0],      ra);
    store_split4(&sAhi[0][rA0 + 64][kA0], &sAlo[0][rA0 + 64][kA0], rb);
    store_split4(&sBhi[0][rB0][nB0],      &sBlo[0][rB0][nB0],      wa);
    store_split4(&sBhi[0][rB0 + 8][nB0],  &sBlo[0][rB0 + 8][nB0],  wb);
    __syncthreads();

    constexpr int ITERS = INC / 16;      // 32
    for (int it = 0; it < ITERS; ++it) {
        const int cur = it & 1;
        if (it + 1 < ITERS) {            // prefetch next slab to registers
            ra = *(const float4*)(Ap0 + (it + 1) * 16);
            rb = *(const float4*)(Ap1 + (it + 1) * 16);
            wa = *(const float4*)(Bp0 + (long)(it + 1) * 16 * NF);
            wb = *(const float4*)(Bp1 + (long)(it + 1) * 16 * NF);
        }

        unsigned bh[4][2], blx[4][2];
#pragma unroll
        for (int nt = 0; nt < 4; nt++) {
            const int n = wn * 32 + nt * 8 + g;
            bh[nt][0]  = pack2(&sBhi[cur][2 * tq][n],     &sBhi[cur][2 * tq + 1][n]);
            bh[nt][1]  = pack2(&sBhi[cur][2 * tq + 8][n], &sBhi[cur][2 * tq + 9][n]);
            blx[nt][0] = pack2(&sBlo[cur][2 * tq][n],     &sBlo[cur][2 * tq + 1][n]);
            blx[nt][1] = pack2(&sBlo[cur][2 * tq + 8][n], &sBlo[cur][2 * tq + 9][n]);
        }
#pragma unroll
        for (int mt = 0; mt < 4; mt++) {
            const int r = wm * 64 + mt * 16 + g;
            unsigned ah[4], al[4];
            ah[0] = *(const unsigned*)&sAhi[cur][r][2 * tq];
            ah[1] = *(const unsigned*)&sAhi[cur][r + 8][2 * tq];
            ah[2] = *(const unsigned*)&sAhi[cur][r][2 * tq + 8];
            ah[3] = *(const unsigned*)&sAhi[cur][r + 8][2 * tq + 8];
            al[0] = *(const unsigned*)&sAlo[cur][r][2 * tq];
            al[1] = *(const unsigned*)&sAlo[cur][r + 8][2 * tq];
            al[2] = *(const unsigned*)&sAlo[cur][r][2 * tq + 8];
            al[3] = *(const unsigned*)&sAlo[cur][r + 8][2 * tq + 8];
#pragma unroll
            for (int nt = 0; nt < 4; nt++) {
                mma16816(acc[mt][nt], ah, bh[nt]);
                mma16816(acc[mt][nt], ah, blx[nt]);
                mma16816(acc[mt][nt], al, bh[nt]);
            }
        }

        if (it + 1 < ITERS) {            // fill the other buffer
            const int nxt = cur ^ 1;
            store_split4(&sAhi[nxt][rA0][kA0],      &sAlo[nxt][rA0][kA0],      ra);
            store_split4(&sAhi[nxt][rA0 + 64][kA0], &sAlo[nxt][rA0 + 64][kA0], rb);
            store_split4(&sBhi[nxt][rB0][nB0],      &sBlo[nxt][rB0][nB0],      wa);
            store_split4(&sBhi[nxt][rB0 + 8][nB0],  &sBlo[nxt][rB0 + 8][nB0],  wb);
        }
        __syncthreads();
    }

#pragma unroll
    for (int mt = 0; mt < 4; mt++) {
        const long row = mbase + wm * 64 + mt * 16 + g;
#pragma unroll
        for (int nt = 0; nt < 4; nt++) {
            const int col = wn * 32 + nt * 8 + 2 * tq;
            *(float2*)&g_XW[row * NF + col]       = make_float2(acc[mt][nt][0], acc[mt][nt][1]);
            *(float2*)&g_XW[(row + 8) * NF + col] = make_float2(acc[mt][nt][2], acc[mt][nt][3]);
        }
    }
}

// ---------------------------------------------------------------------------
// Kernel B: fused rest.  One block = 4 batches (120 rows -> 128 tile).
// An build -> prop1 (MMA) -> GEMM2 (W2 fragments via LDG) -> prop2 (MMA)
// -> Wlin reduce (in-register) -> conv head.  104 KB smem, 2 CTAs/SM.
// ---------------------------------------------------------------------------
__global__ void __launch_bounds__(256, 2) fusedB_kernel(
    const float* __restrict__ graph,
    const float* __restrict__ b1,    const float* __restrict__ b2,
    const float* __restrict__ Wlin,  const float* __restrict__ blin,
    const float* __restrict__ Wconv, const float* __restrict__ bconv,
    float* __restrict__ out)
{
    extern __shared__ __align__(16) char smem[];
    __nv_bfloat16* ch  = (__nv_bfloat16*)(smem + BOFF_CH);
    __nv_bfloat16* cl  = (__nv_bfloat16*)(smem + BOFF_CL);
    __nv_bfloat16* anh = (__nv_bfloat16*)(smem + BOFF_ANH);
    __nv_bfloat16* anl = (__nv_bfloat16*)(smem + BOFF_ANL);
    float*         tmpS= (float*)(smem + BOFF_TMP);
    float*         sdi = (float*)(smem + BOFF_SDI);
    float*         sxp = (float*)(smem + BOFF_SXP);
    float*         sx  = (float*)(smem + BOFF_SX);

    const int tid  = threadIdx.x;
    const int warp = tid >> 5, lane = tid & 31;
    const int wm = warp >> 2, wn = warp & 3;        // GEMM2 warp grid
    const int bq = warp >> 1, nhalf = warp & 1;     // prop warp mapping
    const int g  = lane >> 2, tq = lane & 3;
    const int b0 = blockIdx.x * BPB;
    const long rowbase = (long)b0 * NN;

    // ---- stage XW (split to hi/lo), zero pad rows, An buffers, pattern ----
    for (int idx = tid; idx < 120 * 32; idx += 256) {
        const int r = idx >> 5, c4 = (idx & 31) * 4;
        float4 v = *(const float4*)(g_XW + (rowbase + r) * NF + c4);
        store_split4(ch + r * 136 + c4, cl + r * 136 + c4, v);
    }
    {
        const __nv_bfloat16 z = __float2bfloat16_rn(0.f);
        for (int idx = tid; idx < 8 * 136; idx += 256) {       // rows 120..127
            ch[120 * 136 + idx] = z; cl[120 * 136 + idx] = z;
        }
        for (int idx = tid; idx < BPB * 32 * 36; idx += 256) { // An pad
            anh[idx] = z; anl[idx] = z;
        }
    }
    for (int idx = tid; idx < BPB * 900; idx += 256) {         // adjacency pattern
        const int b = idx / 900, rem = idx - b * 900;
        const float* gb = graph + ((size_t)(b0 + b) * 5) * 900 + rem;
        const float s = gb[0] + gb[900] + gb[1800] + gb[2700] + gb[3600];
        const int i = rem / 30, j = rem - i * 30;
        tmpS[idx] = (s != 0.0f || i == j) ? 1.0f : 0.0f;
    }
    __syncthreads();

    if (tid < BPB * NN) {                                       // dinv
        const int b = tid / NN, i = tid - b * NN;
        const float* rowp = tmpS + b * 900 + i * 30;
        float d = 0.f;
#pragma unroll
        for (int j = 0; j < NN; j++) d += rowp[j];
        sdi[tid] = rsqrtf(d);
    }
    __syncthreads();

    for (int idx = tid; idx < BPB * 900; idx += 256) {          // An -> hi/lo
        const int b = idx / 900, rem = idx - b * 900;
        const int i = rem / 30, j = rem - i * 30;
        const float v = sdi[b * 30 + i] * tmpS[idx] * sdi[b * 30 + j];
        const __nv_bfloat16 h = __float2bfloat16_rn(v);
        anh[(b * 32 + i) * 36 + j] = h;
        anl[(b * 32 + i) * 36 + j] = __float2bfloat16_rn(v - __bfloat162float(h));
    }
    __syncthreads();

    // ---- prop1: H1 = relu(An @ XW + b1) ----
    {
        float pacc[2][8][4];
        prop_mma(anh + bq * 32 * 36, anl + bq * 32 * 36,
                 ch + bq * 30 * 136, cl + bq * 30 * 136, nhalf, g, tq, pacc);
        __syncthreads();    // all XW reads done before overwrite
#pragma unroll
        for (int mt = 0; mt < 2; mt++) {
#pragma unroll
            for (int nt = 0; nt < 8; nt++) {
                const int n = nhalf * 64 + nt * 8 + 2 * tq;
                const float bx = __ldg(b1 + n), by = __ldg(b1 + n + 1);
                const int i0 = mt * 16 + g;
                if (i0 < NN)
                    split_store2(&ch[(bq * 30 + i0) * 136 + n], &cl[(bq * 30 + i0) * 136 + n],
                                 fmaxf(pacc[mt][nt][0] + bx, 0.f),
                                 fmaxf(pacc[mt][nt][1] + by, 0.f));
                const int i1 = i0 + 8;
                if (i1 < NN)
                    split_store2(&ch[(bq * 30 + i1) * 136 + n], &cl[(bq * 30 + i1) * 136 + n],
                                 fmaxf(pacc[mt][nt][2] + bx, 0.f),
                                 fmaxf(pacc[mt][nt][3] + by, 0.f));
            }
        }
        __syncthreads();
    }

    // ---- GEMM2: G = H1 @ W2 (B fragments from pre-packed global) ----
    float acc[4][4][4];
#pragma unroll
    for (int a = 0; a < 4; a++)
#pragma unroll
        for (int b = 0; b < 4; b++)
#pragma unroll
            for (int c = 0; c < 4; c++) acc[a][b][c] = 0.f;

#pragma unroll
    for (int it = 0; it < 8; ++it) {
        const int ko = it * 16 + 2 * tq;
        const int k2a = it * 8 + tq, k2b = it * 8 + tq + 4;
        unsigned bh[4][2], blx[4][2];
#pragma unroll
        for (int nt = 0; nt < 4; nt++) {
            const int n = wn * 32 + nt * 8 + g;
            bh[nt][0]  = __ldg(&g_W2fh[k2a * 128 + n]);
            bh[nt][1]  = __ldg(&g_W2fh[k2b * 128 + n]);
            blx[nt][0] = __ldg(&g_W2fl[k2a * 128 + n]);
            blx[nt][1] = __ldg(&g_W2fl[k2b * 128 + n]);
        }
#pragma unroll
        for (int mt = 0; mt < 4; mt++) {
            const int r = wm * 64 + mt * 16 + g;
            unsigned ah[4], al[4];
            ah[0] = *(const unsigned*)&ch[r * 136 + ko];
            ah[1] = *(const unsigned*)&ch[(r + 8) * 136 + ko];
            ah[2] = *(const unsigned*)&ch[r * 136 + ko + 8];
            ah[3] = *(const unsigned*)&ch[(r + 8) * 136 + ko + 8];
            al[0] = *(const unsigned*)&cl[r * 136 + ko];
            al[1] = *(const unsigned*)&cl[(r + 8) * 136 + ko];
            al[2] = *(const unsigned*)&cl[r * 136 + ko + 8];
            al[3] = *(const unsigned*)&cl[(r + 8) * 136 + ko + 8];
#pragma unroll
            for (int nt = 0; nt < 4; nt++) {
                mma16816(acc[mt][nt], ah, bh[nt]);
                mma16816(acc[mt][nt], ah, blx[nt]);
                mma16816(acc[mt][nt], al, bh[nt]);
            }
        }
    }
    __syncthreads();    // all H1 reads done

    // store G (split) straight from accumulators into ch/cl
#pragma unroll
    for (int mt = 0; mt < 4; mt++) {
        const int row = wm * 64 + mt * 16 + g;
#pragma unroll
        for (int nt = 0; nt < 4; nt++) {
            const int col = wn * 32 + nt * 8 + 2 * tq;
            split_store2(&ch[row * 136 + col],       &cl[row * 136 + col],
                         acc[mt][nt][0], acc[mt][nt][1]);
            split_store2(&ch[(row + 8) * 136 + col], &cl[(row + 8) * 136 + col],
                         acc[mt][nt][2], acc[mt][nt][3]);
        }
    }
    __syncthreads();

    // ---- prop2 + fused Wlin reduction:  x = relu( relu(An@G + b2) @ Wlin + blin )
    {
        float pacc[2][8][4];
        prop_mma(anh + bq * 32 * 36, anl + bq * 32 * 36,
                 ch + bq * 30 * 136, cl + bq * 30 * 136, nhalf, g, tq, pacc);

        float px[4] = {0.f, 0.f, 0.f, 0.f};  // rows g, g+8, g+16, g+24 partials
#pragma unroll
        for (int mt = 0; mt < 2; mt++) {
#pragma unroll
            for (int nt = 0; nt < 8; nt++) {
                const int n = nhalf * 64 + nt * 8 + 2 * tq;
                const float bx  = __ldg(b2 + n),   by  = __ldg(b2 + n + 1);
                const float wlx = __ldg(Wlin + n), wly = __ldg(Wlin + n + 1);
                px[mt * 2 + 0] += fmaxf(pacc[mt][nt][0] + bx, 0.f) * wlx
                                + fmaxf(pacc[mt][nt][1] + by, 0.f) * wly;
                px[mt * 2 + 1] += fmaxf(pacc[mt][nt][2] + bx, 0.f) * wlx
                                + fmaxf(pacc[mt][nt][3] + by, 0.f) * wly;
            }
        }
#pragma unroll
        for (int k = 0; k < 4; k++) {   // reduce over tq (lanes 4g..4g+3)
            px[k] += __shfl_xor_sync(0xffffffffu, px[k], 1);
            px[k] += __shfl_xor_sync(0xffffffffu, px[k], 2);
        }
        if (tq == 0) {
#pragma unroll
            for (int k = 0; k < 4; k++) {
                const int row = (k >> 1) * 16 + (k & 1) * 8 + g;
                if (row < NN) sxp[nhalf * 120 + bq * 30 + row] = px[k];
            }
        }
        __syncthreads();
    }

    if (tid < BPB * NN)
        sx[tid] = fmaxf(sxp[tid] + sxp[120 + tid] + __ldg(blin), 0.f);
    __syncthreads();

    // ---- head: out = x @ Wconv^T + bconv ----
    if (tid < BPB * NC) {
        const int b = tid / NC, c = tid - b * NC;
        float a = __ldg(bconv + c);
#pragma unroll
        for (int i = 0; i < NN; i++) a += sx[b * 30 + i] * __ldg(Wconv + c * 30 + i);
        out[(size_t)(b0 + b) * NC + c] = a;
    }
}

// ---------------------------------------------------------------------------
// Launch
// ---------------------------------------------------------------------------
extern "C" void kernel_launch(void* const* d_in, const int* in_sizes, int n_in,
                              void* d_out, int out_size) {
    const float* real  = (const float*)d_in[0];
    // d_in[1] = imag (unused by the reference)
    const float* graph = (const float*)d_in[2];
    const float* W1    = (const float*)d_in[3];
    const float* b1    = (const float*)d_in[4];
    const float* W2    = (const float*)d_in[5];
    const float* b2    = (const float*)d_in[6];
    const float* Wlin  = (const float*)d_in[7];
    const float* blin  = (const float*)d_in[8];
    const float* Wconv = (const float*)d_in[9];
    const float* bconv = (const float*)d_in[10];
    float* out = (float*)d_out;

    cudaFuncSetAttribute(fusedB_kernel,
                         cudaFuncAttributeMaxDynamicSharedMemorySize, SMEM_B);

    gemm1_kernel<<<MROWS / 128, 256>>>(real, W1);
    init_w2frag<<<32, 256>>>(W2);
    fusedB_kernel<<<NB / BPB, 256, SMEM_B>>>(graph, b1, b2, Wlin, blin,
                                             Wconv, bconv, out);
}